// round 7
// baseline (speedup 1.0000x reference)
#include <cuda_runtime.h>
#include <cstdint>

// Problem constants (fixed shapes): x [4,512,128] -> Q=2048 rows, y [512,128] -> M=512,
// D=128, out [Q, M, 3] f32 (cos, p1, p2).
#define Q_TOT 2048
#define M_TOT 512
#define D_TOT 128

typedef unsigned long long ull;

// ---------------- packed f32x2 helpers (Blackwell-only SASS FFMA2/FADD2) ----------------
__device__ __forceinline__ ull f32x2_add(ull a, ull b) {
    ull r; asm("add.rn.f32x2 %0, %1, %2;" : "=l"(r) : "l"(a), "l"(b)); return r;
}
__device__ __forceinline__ ull f32x2_fma(ull a, ull b, ull c) {
    ull r; asm("fma.rn.f32x2 %0, %1, %2, %3;" : "=l"(r) : "l"(a), "l"(b), "l"(c)); return r;
}
__device__ __forceinline__ ull pack2(float a, float b) {
    ull r; asm("mov.b64 %0, {%1, %2};" : "=l"(r) : "f"(a), "f"(b)); return r;
}
__device__ __forceinline__ float lo32(ull v) { return __uint_as_float((unsigned)v); }
__device__ __forceinline__ float hi32(ull v) { return __uint_as_float((unsigned)(v >> 32)); }

// ---------------- precomputed row norms ----------------
__device__ float g_xn2[Q_TOT];   // ||x_q||^2
__device__ float g_xrn[Q_TOT];   // 1/||x_q||
__device__ float g_yn2[M_TOT];   // ||y_m||^2
__device__ float g_yrn[M_TOT];   // 1/||y_m||

// One warp per row; lane loads exactly one float4 (32*4 = 128 = D).
__global__ void norms_kernel(const float* __restrict__ x, const float* __restrict__ y) {
    int warp = (blockIdx.x * blockDim.x + threadIdx.x) >> 5;
    int lane = threadIdx.x & 31;
    if (warp >= Q_TOT + M_TOT) return;
    const float* row = (warp < Q_TOT) ? (x + (size_t)warp * D_TOT)
                                      : (y + (size_t)(warp - Q_TOT) * D_TOT);
    float4 v = reinterpret_cast<const float4*>(row)[lane];
    float s = v.x * v.x + v.y * v.y + v.z * v.z + v.w * v.w;
    #pragma unroll
    for (int off = 16; off > 0; off >>= 1)
        s += __shfl_xor_sync(0xFFFFFFFFu, s, off);
    if (lane == 0) {
        if (warp < Q_TOT) { g_xn2[warp] = s; g_xrn[warp] = rsqrtf(s); }
        else { int m = warp - Q_TOT; g_yn2[m] = s; g_yrn[m] = rsqrtf(s); }
    }
}

// ---------------- main distance kernel ----------------
// Block: 256 threads = 16 (tx -> m) x 16 (ty -> q). Tile: 64 q x 64 m, 4x4 per thread.
// D processed as 64 f32x2-pairs in 2 chunks of 32, staged in SMEM as [dpair][row].
// y is stored NEGATED so diff = add.f32x2(x2, ny2).
__global__ __launch_bounds__(256) void dist_main(
    const float* __restrict__ x, const float* __restrict__ y, float* __restrict__ out)
{
    __shared__ __align__(16) ull sx[32][65];   // [dpair][q_local], pad to 65 ull (2-bank row shift)
    __shared__ __align__(16) ull sy[32][65];   // [dpair][m_local], holds -y

    const int tid = threadIdx.x;
    const int tx = tid & 15;         // m direction
    const int ty = tid >> 4;         // q direction
    const int q0 = blockIdx.y * 64;
    const int m0 = blockIdx.x * 64;

    ull accL[4][4];  // packed L1 partial sums
    ull accS[4][4];  // packed squared-diff partial sums
    #pragma unroll
    for (int i = 0; i < 4; i++)
        #pragma unroll
        for (int j = 0; j < 4; j++) { accL[i][j] = 0ull; accS[i][j] = 0ull; }

    const float4* x4 = reinterpret_cast<const float4*>(x);
    const float4* y4 = reinterpret_cast<const float4*>(y);

    for (int c = 0; c < 2; ++c) {
        // ---- stage chunk c: 64 rows x 64 floats for each of x/y (coalesced float4 loads) ----
        #pragma unroll
        for (int t = 0; t < 4; ++t) {
            int idx = tid + t * 256;      // 0..1023
            int row = idx >> 4;           // 0..63
            int c4  = idx & 15;           // float4 column within chunk
            float4 vx = x4[(size_t)(q0 + row) * (D_TOT / 4) + c * 16 + c4];
            sx[c4 * 2][row]     = pack2(vx.x, vx.y);
            sx[c4 * 2 + 1][row] = pack2(vx.z, vx.w);
            float4 vy = y4[(size_t)(m0 + row) * (D_TOT / 4) + c * 16 + c4];
            sy[c4 * 2][row]     = pack2(-vy.x, -vy.y);
            sy[c4 * 2 + 1][row] = pack2(-vy.z, -vy.w);
        }
        __syncthreads();

        // ---- compute: 32 dpairs, 16 pairs per thread per dpair ----
        #pragma unroll 8
        for (int dp = 0; dp < 32; ++dp) {
            ull xr[4], yr[4];
            #pragma unroll
            for (int i = 0; i < 4; i++) xr[i] = sx[dp][ty * 4 + i];
            #pragma unroll
            for (int j = 0; j < 4; j++) yr[j] = sy[dp][tx * 4 + j];
            #pragma unroll
            for (int i = 0; i < 4; i++) {
                #pragma unroll
                for (int j = 0; j < 4; j++) {
                    ull d  = f32x2_add(xr[i], yr[j]);            // x - y (packed)
                    ull ad = d & 0x7FFFFFFF7FFFFFFFull;          // packed |.| (2x LOP3, alu pipe)
                    accL[i][j] = f32x2_add(accL[i][j], ad);
                    accS[i][j] = f32x2_fma(d, d, accS[i][j]);
                }
            }
        }
        __syncthreads();
    }

    // ---- epilogue: fold packed halves, derive cos via polarization identity ----
    float xn2[4], xrn[4], yn2[4], yrn[4];
    #pragma unroll
    for (int i = 0; i < 4; i++) {
        int q = q0 + ty * 4 + i;
        xn2[i] = g_xn2[q]; xrn[i] = g_xrn[q];
    }
    #pragma unroll
    for (int j = 0; j < 4; j++) {
        int m = m0 + tx * 4 + j;
        yn2[j] = g_yn2[m]; yrn[j] = g_yrn[m];
    }

    #pragma unroll
    for (int i = 0; i < 4; i++) {
        int q = q0 + ty * 4 + i;
        float r[12];
        #pragma unroll
        for (int j = 0; j < 4; j++) {
            float l1 = lo32(accL[i][j]) + hi32(accL[i][j]);
            float sq = lo32(accS[i][j]) + hi32(accS[i][j]);
            float p2 = sqrtf(sq);
            // x.y = (||x||^2 + ||y||^2 - ||x-y||^2) / 2 ; cos = x.y / (||x|| ||y||)
            float cs = (xn2[i] + yn2[j] - sq) * 0.5f * xrn[i] * yrn[j];
            r[3 * j + 0] = cs;
            r[3 * j + 1] = l1;
            r[3 * j + 2] = p2;
        }
        // 4 consecutive m -> 12 contiguous floats, 48B-aligned: 3x STG.128
        float4* o = reinterpret_cast<float4*>(out + ((size_t)q * M_TOT + (m0 + tx * 4)) * 3);
        o[0] = make_float4(r[0], r[1], r[2],  r[3]);
        o[1] = make_float4(r[4], r[5], r[6],  r[7]);
        o[2] = make_float4(r[8], r[9], r[10], r[11]);
    }
}

extern "C" void kernel_launch(void* const* d_in, const int* in_sizes, int n_in,
                              void* d_out, int out_size) {
    const float* x = (const float*)d_in[0];   // [4,512,128]
    const float* y = (const float*)d_in[1];   // [512,128]
    float* out = (float*)d_out;               // [4,512,512,3]

    // 2560 rows, 8 warps/block -> 320 blocks
    norms_kernel<<<320, 256>>>(x, y);

    dim3 grid(M_TOT / 64, Q_TOT / 64);        // (8, 32) = 256 blocks
    dist_main<<<grid, 256>>>(x, y, out);
}